// round 14
// baseline (speedup 1.0000x reference)
#include <cuda_runtime.h>
#include <cuda_fp16.h>
#include <cstdint>

// CompressionLayer grouped GEMM via mma.sync fp16 (f32 accumulate),
// BARRIER-FREE mainloop: A (X) fragments gathered straight from gmem into
// registers (LDG.64 per fragment pair, sector-perfect), converted in-reg;
// only W lives in smem (fp16, one prologue sync). Warps free-run on
// scoreboards -> continuous DRAM stream, no stage quantization.
// One CTA per chunk n: D[256,64] = X[256,256]*W[64,256]^T, two 128-batch
// halves, warp grid 4(m) x 2(n), warp tile m32 x n32.

#define NTHREADS 256

// smem layout
#define S_W     0        // 64 rows x 512B (256 fp16), swizzled
#define S_BIAS  32768    // 64 f32
#define S_TOTAL 33024

static __device__ __forceinline__ uint32_t smem_u32(const void* p) {
    uint32_t a;
    asm("{ .reg .u64 t; cvta.to.shared.u64 t, %1; cvt.u32.u64 %0, t; }"
        : "=r"(a) : "l"(p));
    return a;
}

static __device__ __forceinline__ void ldmatrix_x4(uint32_t& a0, uint32_t& a1,
                                                   uint32_t& a2, uint32_t& a3,
                                                   uint32_t addr) {
    asm volatile("ldmatrix.sync.aligned.m8n8.x4.shared.b16 {%0,%1,%2,%3}, [%4];"
                 : "=r"(a0), "=r"(a1), "=r"(a2), "=r"(a3) : "r"(addr));
}

static __device__ __forceinline__ void mma16816(float* c, uint32_t a0, uint32_t a1,
                                                uint32_t a2, uint32_t a3,
                                                uint32_t b0, uint32_t b1) {
    asm volatile(
        "mma.sync.aligned.m16n8k16.row.col.f32.f16.f16.f32 "
        "{%0,%1,%2,%3}, {%4,%5,%6,%7}, {%8,%9}, {%0,%1,%2,%3};"
        : "+f"(c[0]), "+f"(c[1]), "+f"(c[2]), "+f"(c[3])
        : "r"(a0), "r"(a1), "r"(a2), "r"(a3), "r"(b0), "r"(b1));
}

static __device__ __forceinline__ uint32_t f2h2(float2 v) {
    __half2 h = __floats2half2_rn(v.x, v.y);
    return *reinterpret_cast<uint32_t*>(&h);
}

// f32x4 -> fp16x4, 8B store into swizzled W row (512B stride)
static __device__ __forceinline__ void cvt_store_w(char* dst, int row, int kcol,
                                                   float4 v) {
    __half2 h01 = __floats2half2_rn(v.x, v.y);
    __half2 h23 = __floats2half2_rn(v.z, v.w);
    int phys = row * 512 + ((kcol * 2) ^ ((row & 7) << 4));
    *reinterpret_cast<uint2*>(dst + phys) =
        make_uint2(*(uint32_t*)&h01, *(uint32_t*)&h23);
}

__global__ void __launch_bounds__(NTHREADS, 2)
compression_mma_kernel(const float* __restrict__ xg,
                       const float* __restrict__ Wg,
                       const float* __restrict__ bkg,
                       float* __restrict__ out) {
    extern __shared__ char sm[];
    const uint32_t sb = smem_u32(sm);
    const int tid = threadIdx.x;
    const int wid = tid >> 5;
    const int lid = tid & 31;

    const int n  = blockIdx.x;      // 0..1023
    const int ch = n >> 5;
    const int cw = n & 31;

    // ---- prologue: W[n] 64x256 f32 -> fp16 smem (once), bias ----
    {
        const float4* Wg4 = reinterpret_cast<const float4*>(Wg + (size_t)n * 64 * 256);
        #pragma unroll
        for (int it = 0; it < 16; ++it) {
            int e  = tid + it * NTHREADS;   // 0..4095
            int o  = e >> 6;
            int k4 = (e & 63) << 2;
            cvt_store_w(sm + S_W, o, k4, Wg4[e]);
        }
    }
    if (tid < 64)
        reinterpret_cast<float*>(sm + S_BIAS)[tid] = bkg[n * 64 + tid];
    __syncthreads();    // the ONLY barrier

    // ---- warp tiling: 4(m) x 2(n), warp tile m32 x n32 ----
    const int wm = (wid & 3) << 5;      // 0/32/64/96
    const int wn = (wid >> 2) << 5;     // 0/32
    const int g  = lid >> 2;            // 0..7
    const int t  = lid & 3;             // 0..3

    // B (W) ldmatrix lane addressing (validated in R10)
    const int bn0 = wn + ((lid >> 4) << 3) + (lid & 7);
    const int bn1 = bn0 + 16;
    const uint32_t b0_base = sb + S_W + bn0 * 512;
    const uint32_t b1_base = sb + S_W + bn1 * 512;
    const uint32_t b0_sw   = (uint32_t)(bn0 & 7) << 4;
    const uint32_t b1_sw   = (uint32_t)(bn1 & 7) << 4;
    const uint32_t b_coff  = (uint32_t)((lid >> 3) & 1) << 4;  // 0 / 16

    // A gmem gather base: k-step s = chunk row i; j = 2t (+1 from float2).
    // fragment pairs: (g,2t) (g+8,2t) (g,2t+8) (g+8,2t+8) per m16 subtile.
    const float* pa = xg + (size_t)(ch * 16) * 512 + cw * 16
                         + (size_t)(wm + g) * 262144 + 2 * t;

    float acc[2][4][4];
    #pragma unroll
    for (int i = 0; i < 2; ++i)
        #pragma unroll
        for (int j = 0; j < 4; ++j)
            #pragma unroll
            for (int e = 0; e < 4; ++e) acc[i][j][e] = 0.f;

    // load the 8 float2 fragment sources for (bt, kstep s)
    auto ldg_step = [&](float2* L, int bt, int s) {
        const float* p = pa + (size_t)(bt * 128) * 262144 + s * 512;
        #pragma unroll
        for (int mt = 0; mt < 2; ++mt) {
            const float* q = p + (size_t)(mt * 16) * 262144;
            L[mt * 4 + 0] = *reinterpret_cast<const float2*>(q);              // (g,   jlo)
            L[mt * 4 + 1] = *reinterpret_cast<const float2*>(q + 8);          // (g,   jhi)
            L[mt * 4 + 2] = *reinterpret_cast<const float2*>(q + (size_t)8 * 262144);     // (g+8, jlo)
            L[mt * 4 + 3] = *reinterpret_cast<const float2*>(q + (size_t)8 * 262144 + 8); // (g+8, jhi)
        }
    };

    auto epilogue = [&](int bt) {
        const float* Bs = reinterpret_cast<const float*>(sm + S_BIAS);
        #pragma unroll
        for (int mt = 0; mt < 2; ++mt) {
            #pragma unroll
            for (int nt = 0; nt < 4; ++nt) {
                int ob  = wn + nt * 8;
                int oi  = ob >> 3;
                int oj  = 2 * t;
                float bi0 = Bs[ob + oj];
                float bi1 = Bs[ob + oj + 1];

                size_t colofs = (size_t)(ch * 8 + oi) * 256 + cw * 8 + oj;
                int bg0 = bt * 128 + wm + mt * 16 + g;
                float2 w0 = make_float2(fmaxf(acc[mt][nt][0] + bi0, 0.f),
                                        fmaxf(acc[mt][nt][1] + bi1, 0.f));
                *reinterpret_cast<float2*>(out + (size_t)bg0 * 65536 + colofs) = w0;

                int bg1 = bg0 + 8;
                float2 w1 = make_float2(fmaxf(acc[mt][nt][2] + bi0, 0.f),
                                        fmaxf(acc[mt][nt][3] + bi1, 0.f));
                *reinterpret_cast<float2*>(out + (size_t)bg1 * 65536 + colofs) = w1;
            }
        }
    };

    // ---- barrier-free mainloop: 32 k-steps (2 batch halves x 16) ----
    float2 La[8], Lb[8];
    ldg_step(La, 0, 0);

    #pragma unroll
    for (int ks = 0; ks < 32; ++ks) {
        const int bt = ks >> 4;
        const int s  = ks & 15;
        float2* Lc = (ks & 1) ? Lb : La;
        float2* Ln = (ks & 1) ? La : Lb;

        if (ks < 31) ldg_step(Ln, (ks + 1) >> 4, (ks + 1) & 15);

        // convert current fragments: mma A order = {klo(g), klo(g+8), khi(g), khi(g+8)}
        uint32_t xa[2][4];
        #pragma unroll
        for (int mt = 0; mt < 2; ++mt) {
            xa[mt][0] = f2h2(Lc[mt * 4 + 0]);
            xa[mt][1] = f2h2(Lc[mt * 4 + 2]);
            xa[mt][2] = f2h2(Lc[mt * 4 + 1]);
            xa[mt][3] = f2h2(Lc[mt * 4 + 3]);
        }

        const uint32_t colB = ((uint32_t)s << 5) | b_coff;
        uint32_t u0, u1, u2, u3, v0, v1, v2, v3;
        ldmatrix_x4(u0, u1, u2, u3, b0_base + (colB ^ b0_sw));
        ldmatrix_x4(v0, v1, v2, v3, b1_base + (colB ^ b1_sw));

        mma16816(acc[0][0], xa[0][0], xa[0][1], xa[0][2], xa[0][3], u0, u1);
        mma16816(acc[0][1], xa[0][0], xa[0][1], xa[0][2], xa[0][3], u2, u3);
        mma16816(acc[0][2], xa[0][0], xa[0][1], xa[0][2], xa[0][3], v0, v1);
        mma16816(acc[0][3], xa[0][0], xa[0][1], xa[0][2], xa[0][3], v2, v3);
        mma16816(acc[1][0], xa[1][0], xa[1][1], xa[1][2], xa[1][3], u0, u1);
        mma16816(acc[1][1], xa[1][0], xa[1][1], xa[1][2], xa[1][3], u2, u3);
        mma16816(acc[1][2], xa[1][0], xa[1][1], xa[1][2], xa[1][3], v0, v1);
        mma16816(acc[1][3], xa[1][0], xa[1][1], xa[1][2], xa[1][3], v2, v3);

        if (s == 15) {
            epilogue(bt);
            if (bt == 0) {
                #pragma unroll
                for (int i = 0; i < 2; ++i)
                    #pragma unroll
                    for (int j = 0; j < 4; ++j)
                        #pragma unroll
                        for (int e = 0; e < 4; ++e) acc[i][j][e] = 0.f;
            }
        }
    }
}

extern "C" void kernel_launch(void* const* d_in, const int* in_sizes, int n_in,
                              void* d_out, int out_size) {
    const float* x  = (const float*)d_in[0];   // [256,512,512]
    const float* Wk = (const float*)d_in[1];   // [1024,64,256]
    const float* bk = (const float*)d_in[2];   // [1024,64]
    float* out = (float*)d_out;                // [256, 65536]

    cudaFuncSetAttribute(compression_mma_kernel,
                         cudaFuncAttributeMaxDynamicSharedMemorySize, S_TOTAL);

    compression_mma_kernel<<<1024, NTHREADS, S_TOTAL>>>(x, Wk, bk, out);
}

// round 15
// speedup vs baseline: 1.8687x; 1.8687x over previous
#include <cuda_runtime.h>
#include <cstdint>

// CompressionLayer grouped GEMM via mma.sync TF32 (f32 accumulate) with
// cp.async (LDGSTS) staging -- no register staging, no conversion on the
// X path (tf32 rounding in-register before MMA).
// y[b,n,o] = relu( sum_k x[b,n,k] * Wk[n,o,k] + bk[n,o] )
// One CTA per chunk n: D[256,64] = X[256,256]*W[64,256]^T, two 128-batch
// halves; X streamed in 16 k-stages of 32 through a 3-buffer cp.async ring
// (2 stages in flight during compute). W stored once in smem as
// tf32-rounded f32. Warp grid 4(m) x 2(n), warp tile m32 x n32.

#define NTHREADS 256

// smem layout (bytes)
#define S_W      0        // 64 rows x 1024B (256 f32), 16B-quad XOR swizzled
#define S_X      65536    // 3 stage bufs: 128 rows x 128B (k=32 f32)
#define S_STAGE  16384
#define S_TOTAL  114688   // = 14 * 8192 exactly

static __device__ __forceinline__ uint32_t smem_u32(const void* p) {
    uint32_t a;
    asm("{ .reg .u64 t; cvta.to.shared.u64 t, %1; cvt.u32.u64 %0, t; }"
        : "=r"(a) : "l"(p));
    return a;
}

static __device__ __forceinline__ uint32_t lds32(uint32_t addr) {
    uint32_t v;
    asm volatile("ld.shared.b32 %0, [%1];" : "=r"(v) : "r"(addr));
    return v;
}

static __device__ __forceinline__ uint32_t cvt_tf32(float f) {
    uint32_t r;
    asm("cvt.rna.tf32.f32 %0, %1;" : "=r"(r) : "f"(f));
    return r;
}

static __device__ __forceinline__ uint32_t lds_tf32(uint32_t addr) {
    return cvt_tf32(__uint_as_float(lds32(addr)));
}

static __device__ __forceinline__ void mma_tf32(float* c, uint32_t a0, uint32_t a1,
                                                uint32_t a2, uint32_t a3,
                                                uint32_t b0, uint32_t b1) {
    asm volatile(
        "mma.sync.aligned.m16n8k8.row.col.f32.tf32.tf32.f32 "
        "{%0,%1,%2,%3}, {%4,%5,%6,%7}, {%8,%9}, {%0,%1,%2,%3};"
        : "+f"(c[0]), "+f"(c[1]), "+f"(c[2]), "+f"(c[3])
        : "r"(a0), "r"(a1), "r"(a2), "r"(a3), "r"(b0), "r"(b1));
}

__global__ void __launch_bounds__(NTHREADS, 2)
compression_mma_kernel(const float* __restrict__ xg,
                       const float* __restrict__ Wg,
                       const float* __restrict__ bkg,
                       float* __restrict__ out) {
    extern __shared__ char sm[];
    const uint32_t sb = smem_u32(sm);
    const int tid = threadIdx.x;
    const int wid = tid >> 5;
    const int lid = tid & 31;

    const int n  = blockIdx.x;      // 0..1023
    const int ch = n >> 5;
    const int cw = n & 31;
    const float* xbase = xg + (size_t)(ch * 16) * 512 + cw * 16;

    // cp.async stage issue: stage st covers bt = st>>3, chunk rows 2*(st&7)+{0,1}.
    // 256 threads x 4 x 16B; 4 lanes cover one full 64B chunk row (coalesced).
    #define ISSUE(st)                                                          \
        {                                                                      \
            const uint32_t dstb = sb + S_X + ((st) % 3) * S_STAGE;             \
            _Pragma("unroll")                                                  \
            for (int il = 0; il < 4; ++il) {                                   \
                int c  = il * 256 + tid;                                       \
                int q  = c & 3;                                                \
                int b  = (c >> 2) & 127;                                       \
                int ri = c >> 9;                                               \
                const float* src = xbase +                                     \
                    (size_t)(((st) >> 3) * 128 + b) * 262144 +                 \
                    (((st) & 7) * 2 + ri) * 512 + q * 4;                       \
                uint32_t dst = dstb + b * 128 +                                \
                    (uint32_t)(((ri * 64 + q * 16)) ^ ((b & 7) << 4));         \
                asm volatile("cp.async.cg.shared.global [%0], [%1], 16;"       \
                             :: "r"(dst), "l"(src));                           \
            }                                                                  \
            asm volatile("cp.async.commit_group;" ::: "memory");               \
        }

    // prime two stages
    ISSUE(0);
    ISSUE(1);

    // ---- W[n] 64x256 f32 -> tf32-rounded f32 smem (once), overlapped ----
    {
        const float4* Wg4 = reinterpret_cast<const float4*>(Wg + (size_t)n * 64 * 256);
        #pragma unroll
        for (int it = 0; it < 16; ++it) {
            int e  = tid + it * NTHREADS;   // 0..4095
            int o  = e >> 6;
            int k4 = (e & 63) << 2;         // k, multiple of 4
            float4 v = Wg4[e];
            uint4 r;
            r.x = cvt_tf32(v.x);
            r.y = cvt_tf32(v.y);
            r.z = cvt_tf32(v.z);
            r.w = cvt_tf32(v.w);
            *reinterpret_cast<uint4*>(sm + S_W + o * 1024 +
                                      ((k4 * 4) ^ ((o & 7) << 4))) = r;
        }
    }

    // ---- compute lane addressing: 4(m) x 2(n) warps, m32 x n32 tiles ----
    const int wm = (wid & 3) << 5;      // 0/32/64/96
    const int wn = (wid >> 2) << 5;     // 0/32
    const int g  = lid >> 2;            // 0..7
    const int t  = lid & 3;             // 0..3
    const uint32_t gsw = (uint32_t)g << 4;

    // A row bases within a stage buffer (rows: wm+g, wm+g+8, wm+16+g, wm+24+g)
    const uint32_t ar0 = (uint32_t)(wm + g) * 128;
    const uint32_t ar1 = ar0 + 8 * 128;
    const uint32_t ar2 = ar0 + 16 * 128;
    const uint32_t ar3 = ar0 + 24 * 128;

    // B (W) row bases: o = wn + nb*8 + g
    uint32_t wb[4];
    #pragma unroll
    for (int nb = 0; nb < 4; ++nb)
        wb[nb] = sb + S_W + (uint32_t)(wn + nb * 8 + g) * 1024;

    float acc[2][4][4];
    #pragma unroll
    for (int i = 0; i < 2; ++i)
        #pragma unroll
        for (int j = 0; j < 4; ++j)
            #pragma unroll
            for (int e = 0; e < 4; ++e) acc[i][j][e] = 0.f;

    auto epilogue = [&](int bt) {
        #pragma unroll
        for (int mt = 0; mt < 2; ++mt) {
            #pragma unroll
            for (int nt = 0; nt < 4; ++nt) {
                int ob  = wn + nt * 8;
                int oi  = ob >> 3;
                int oj  = 2 * t;
                float bi0 = bkg[n * 64 + ob + oj];
                float bi1 = bkg[n * 64 + ob + oj + 1];

                size_t colofs = (size_t)(ch * 8 + oi) * 256 + cw * 8 + oj;
                int bg0 = bt * 128 + wm + mt * 16 + g;
                float2 w0 = make_float2(fmaxf(acc[mt][nt][0] + bi0, 0.f),
                                        fmaxf(acc[mt][nt][1] + bi1, 0.f));
                *reinterpret_cast<float2*>(out + (size_t)bg0 * 65536 + colofs) = w0;

                int bg1 = bg0 + 8;
                float2 w1 = make_float2(fmaxf(acc[mt][nt][2] + bi0, 0.f),
                                        fmaxf(acc[mt][nt][3] + bi1, 0.f));
                *reinterpret_cast<float2*>(out + (size_t)bg1 * 65536 + colofs) = w1;
            }
        }
    };

    // ---- 16-stage mainloop: wait -> sync -> issue(st+2) -> compute(st) ----
    #pragma unroll 1
    for (int st = 0; st < 16; ++st) {
        if (st < 15) {
            asm volatile("cp.async.wait_group 1;" ::: "memory");
        } else {
            asm volatile("cp.async.wait_group 0;" ::: "memory");
        }
        __syncthreads();   // stage st visible to all; buffer (st-1)%3 free

        if (st < 14) ISSUE(st + 2);

        const uint32_t xb = sb + S_X + (st % 3) * S_STAGE;
        const int s8 = st & 7;

        #pragma unroll
        for (int ko = 0; ko < 4; ++ko) {
            // A fragments (tf32-rounded after LDS)
            const uint32_t abase = (uint32_t)(ko * 8 + t) * 4;
            const uint32_t alo = abase ^ gsw;
            const uint32_t ahi = (abase + 16) ^ gsw;
            uint32_t A0[4], A1[4];
            A0[0] = lds_tf32(xb + ar0 + alo);
            A0[1] = lds_tf32(xb + ar1 + alo);
            A0[2] = lds_tf32(xb + ar0 + ahi);
            A0[3] = lds_tf32(xb + ar1 + ahi);
            A1[0] = lds_tf32(xb + ar2 + alo);
            A1[1] = lds_tf32(xb + ar3 + alo);
            A1[2] = lds_tf32(xb + ar2 + ahi);
            A1[3] = lds_tf32(xb + ar3 + ahi);

            // B fragments (already tf32-rounded at store)
            const uint32_t bbase = (uint32_t)((s8 * 32 + ko * 8 + t) * 4);
            const uint32_t blo = bbase ^ gsw;
            const uint32_t bhi = (bbase + 16) ^ gsw;
            uint32_t B0[4], B1[4];
            #pragma unroll
            for (int nb = 0; nb < 4; ++nb) {
                B0[nb] = lds32(wb[nb] + blo);
                B1[nb] = lds32(wb[nb] + bhi);
            }

            #pragma unroll
            for (int nb = 0; nb < 4; ++nb) {
                mma_tf32(acc[0][nb], A0[0], A0[1], A0[2], A0[3], B0[nb], B1[nb]);
                mma_tf32(acc[1][nb], A1[0], A1[1], A1[2], A1[3], B0[nb], B1[nb]);
            }
        }

        if (st == 7) {
            epilogue(0);
            #pragma unroll
            for (int i = 0; i < 2; ++i)
                #pragma unroll
                for (int j = 0; j < 4; ++j)
                    #pragma unroll
                    for (int e = 0; e < 4; ++e) acc[i][j][e] = 0.f;
        }
    }
    epilogue(1);

    #undef ISSUE
}

extern "C" void kernel_launch(void* const* d_in, const int* in_sizes, int n_in,
                              void* d_out, int out_size) {
    const float* x  = (const float*)d_in[0];   // [256,512,512]
    const float* Wk = (const float*)d_in[1];   // [1024,64,256]
    const float* bk = (const float*)d_in[2];   // [1024,64]
    float* out = (float*)d_out;                // [256, 65536]

    cudaFuncSetAttribute(compression_mma_kernel,
                         cudaFuncAttributeMaxDynamicSharedMemorySize, S_TOTAL);

    compression_mma_kernel<<<1024, NTHREADS, S_TOTAL>>>(x, Wk, bk, out);
}

// round 17
// speedup vs baseline: 2.4692x; 1.3213x over previous
#include <cuda_runtime.h>
#include <cuda_fp16.h>
#include <cstdint>

// CompressionLayer grouped GEMM via mma.sync fp16 (f32 accumulate).
// y[b,n,o] = relu( sum_k x[b,n,k] * Wk[n,o,k] + bk[n,o] )
// WARP-PRIVATE cp.async pipeline, zero CTA barriers in the mainloop:
// warp grid 8(m) x 1(n) covers all 256 batches (warp w: rows 32w..32w+31),
// warp tile m32 x n64, 16 k16 stages over K=256, SINGLE epilogue.
// Each warp streams its own 32 batches through a private 4-stage f32 smem
// ring (cp.async.cg 16B; wait_group + __syncwarp only).
// A fragments: 8x LDS.64 + cvt.f16x2 per k16 (XOR-swizzle conflict-free).
// W: fp16 smem + ldmatrix (converted once; single prologue barrier).
// One CTA per chunk n: D[256,64] = X[256,256]*W[64,256]^T.

#define NTHREADS 256

// smem layout (bytes)
#define S_W     0        // 64 rows x 512B (256 fp16), XOR-quad swizzled
#define S_BIAS  32768    // 64 f32
#define S_X     33792    // 8 warps x (4 stages x 2048B) private rings
#define WRING   8192
#define S_TOTAL 99328

static __device__ __forceinline__ uint32_t smem_u32(const void* p) {
    uint32_t a;
    asm("{ .reg .u64 t; cvta.to.shared.u64 t, %1; cvt.u32.u64 %0, t; }"
        : "=r"(a) : "l"(p));
    return a;
}

static __device__ __forceinline__ void ldmatrix_x4(uint32_t& a0, uint32_t& a1,
                                                   uint32_t& a2, uint32_t& a3,
                                                   uint32_t addr) {
    asm volatile("ldmatrix.sync.aligned.m8n8.x4.shared.b16 {%0,%1,%2,%3}, [%4];"
                 : "=r"(a0), "=r"(a1), "=r"(a2), "=r"(a3) : "r"(addr));
}

static __device__ __forceinline__ void mma16816(float* c, uint32_t a0, uint32_t a1,
                                                uint32_t a2, uint32_t a3,
                                                uint32_t b0, uint32_t b1) {
    asm volatile(
        "mma.sync.aligned.m16n8k16.row.col.f32.f16.f16.f32 "
        "{%0,%1,%2,%3}, {%4,%5,%6,%7}, {%8,%9}, {%0,%1,%2,%3};"
        : "+f"(c[0]), "+f"(c[1]), "+f"(c[2]), "+f"(c[3])
        : "r"(a0), "r"(a1), "r"(a2), "r"(a3), "r"(b0), "r"(b1));
}

static __device__ __forceinline__ uint32_t lds64_h2(uint32_t addr) {
    float2 f;
    asm volatile("ld.shared.v2.f32 {%0,%1}, [%2];"
                 : "=f"(f.x), "=f"(f.y) : "r"(addr));
    __half2 h = __floats2half2_rn(f.x, f.y);
    return *reinterpret_cast<uint32_t*>(&h);
}

// f32x4 -> fp16x4, 8B store into swizzled W row (512B stride)
static __device__ __forceinline__ void cvt_store_w(char* dst, int row, int kcol,
                                                   float4 v) {
    __half2 h01 = __floats2half2_rn(v.x, v.y);
    __half2 h23 = __floats2half2_rn(v.z, v.w);
    int phys = row * 512 + ((kcol * 2) ^ ((row & 7) << 4));
    *reinterpret_cast<uint2*>(dst + phys) =
        make_uint2(*(uint32_t*)&h01, *(uint32_t*)&h23);
}

__global__ void __launch_bounds__(NTHREADS, 2)
compression_mma_kernel(const float* __restrict__ xg,
                       const float* __restrict__ Wg,
                       const float* __restrict__ bkg,
                       float* __restrict__ out) {
    extern __shared__ char sm[];
    const uint32_t sb = smem_u32(sm);
    const int tid = threadIdx.x;
    const int wid = tid >> 5;
    const int lid = tid & 31;

    const int n  = blockIdx.x;      // 0..1023
    const int ch = n >> 5;
    const int cw = n & 31;

    const int wm = wid << 5;        // warp's 32 batch rows (0..224)
    const int g  = lid >> 2;        // 0..7
    const int t  = lid & 3;         // 0..3

    // warp-private X source/ring bases
    const float* xsrc = xg + (size_t)(ch * 16) * 512 + cw * 16
                           + (size_t)wm * 262144;
    const uint32_t xwb = sb + S_X + wid * WRING;
    const int cp_b = lid >> 2;              // row within 8-row group (0..7)
    const int cp_q = lid & 3;               // 16B quad
    const uint32_t cp_sw = (uint32_t)(cp_b & 3) << 4;

    // issue one k16 stage (ks = chunk row i, 0..15); ALWAYS commits
    // (empty group when ks>=16) so wait_group 3 is uniform.
    #define ISSUE(ks)                                                          \
        {                                                                      \
            if ((ks) < 16) {                                                   \
                const uint32_t dstb = xwb + ((ks) & 3) * 2048;                 \
                const float* srcb = xsrc + (ks) * 512;                         \
                _Pragma("unroll")                                              \
                for (int il = 0; il < 4; ++il) {                               \
                    int b = il * 8 + cp_b;                                     \
                    const float* s = srcb + (size_t)b * 262144 + cp_q * 4;     \
                    uint32_t d = dstb + b * 64 + (((uint32_t)cp_q * 16) ^ cp_sw); \
                    asm volatile("cp.async.cg.shared.global [%0], [%1], 16;"   \
                                 :: "r"(d), "l"(s));                           \
                }                                                              \
            }                                                                  \
            asm volatile("cp.async.commit_group;" ::: "memory");               \
        }

    // prime 3 stages
    ISSUE(0); ISSUE(1); ISSUE(2);

    // ---- prologue: W[n] 64x256 f32 -> fp16 smem (once), bias ----
    {
        const float4* Wg4 = reinterpret_cast<const float4*>(Wg + (size_t)n * 64 * 256);
        #pragma unroll
        for (int it = 0; it < 16; ++it) {
            int e  = tid + it * NTHREADS;   // 0..4095
            int o  = e >> 6;
            int k4 = (e & 63) << 2;
            cvt_store_w(sm + S_W, o, k4, Wg4[e]);
        }
    }
    if (tid < 64)
        reinterpret_cast<float*>(sm + S_BIAS)[tid] = bkg[n * 64 + tid];
    __syncthreads();    // the ONLY CTA barrier

    // A LDS addressing: rows g+8m within the warp's 32, swizzle per (g&3)
    const uint32_t a_sw = (uint32_t)(g & 3) << 4;
    const uint32_t a_c0 = ((uint32_t)(8 * t)) ^ a_sw;        // k lo half
    const uint32_t a_c1 = ((uint32_t)(8 * t + 32)) ^ a_sw;   // k hi half

    // B (W) ldmatrix lane addressing, 4 n16 tiles covering n64
    uint32_t bbase[4], bsw[4];
    #pragma unroll
    for (int j = 0; j < 4; ++j) {
        int bn = j * 16 + ((lid >> 4) << 3) + (lid & 7);
        bbase[j] = sb + S_W + bn * 512;
        bsw[j]   = (uint32_t)(bn & 7) << 4;
    }
    const uint32_t b_coff = (uint32_t)((lid >> 3) & 1) << 4;

    float acc[2][8][4];
    #pragma unroll
    for (int i = 0; i < 2; ++i)
        #pragma unroll
        for (int j = 0; j < 8; ++j)
            #pragma unroll
            for (int e = 0; e < 4; ++e) acc[i][j][e] = 0.f;

    // ---- barrier-free mainloop: 16 k16 steps over K=256 ----
    #pragma unroll
    for (int ks = 0; ks < 16; ++ks) {
        ISSUE(ks + 3);
        asm volatile("cp.async.wait_group 3;" ::: "memory");
        __syncwarp();

        const uint32_t xb = xwb + (ks & 3) * 2048;

        // A fragments: m32 x k16, f32 smem -> fp16x2 regs
        uint32_t xa[2][4];
        #pragma unroll
        for (int mt = 0; mt < 2; ++mt) {
            uint32_t r0 = xb + (uint32_t)(mt * 16 + g) * 64;
            uint32_t r1 = r0 + 8 * 64;
            xa[mt][0] = lds64_h2(r0 + a_c0);
            xa[mt][1] = lds64_h2(r1 + a_c0);
            xa[mt][2] = lds64_h2(r0 + a_c1);
            xa[mt][3] = lds64_h2(r1 + a_c1);
        }

        // B fragments + MMAs, n64 in 4 n16 tiles
        const uint32_t colB = ((uint32_t)ks << 5) | b_coff;
        #pragma unroll
        for (int j = 0; j < 4; ++j) {
            uint32_t u0, u1, u2, u3;
            ldmatrix_x4(u0, u1, u2, u3, bbase[j] + (colB ^ bsw[j]));
            mma16816(acc[0][2 * j],     xa[0][0], xa[0][1], xa[0][2], xa[0][3], u0, u1);
            mma16816(acc[0][2 * j + 1], xa[0][0], xa[0][1], xa[0][2], xa[0][3], u2, u3);
            mma16816(acc[1][2 * j],     xa[1][0], xa[1][1], xa[1][2], xa[1][3], u0, u1);
            mma16816(acc[1][2 * j + 1], xa[1][0], xa[1][1], xa[1][2], xa[1][3], u2, u3);
        }
    }

    // ---- single epilogue: bias + relu, scatter ----
    {
        const float* Bs = reinterpret_cast<const float*>(sm + S_BIAS);
        #pragma unroll
        for (int mt = 0; mt < 2; ++mt) {
            #pragma unroll
            for (int nt = 0; nt < 8; ++nt) {
                int ob  = nt * 8;
                int oi  = nt;
                int oj  = 2 * t;
                float bi0 = Bs[ob + oj];
                float bi1 = Bs[ob + oj + 1];

                size_t colofs = (size_t)(ch * 8 + oi) * 256 + cw * 8 + oj;
                int bg0 = wm + mt * 16 + g;
                float2 w0 = make_float2(fmaxf(acc[mt][nt][0] + bi0, 0.f),
                                        fmaxf(acc[mt][nt][1] + bi1, 0.f));
                *reinterpret_cast<float2*>(out + (size_t)bg0 * 65536 + colofs) = w0;

                int bg1 = bg0 + 8;
                float2 w1 = make_float2(fmaxf(acc[mt][nt][2] + bi0, 0.f),
                                        fmaxf(acc[mt][nt][3] + bi1, 0.f));
                *reinterpret_cast<float2*>(out + (size_t)bg1 * 65536 + colofs) = w1;
            }
        }
    }

    #undef ISSUE
}

extern "C" void kernel_launch(void* const* d_in, const int* in_sizes, int n_in,
                              void* d_out, int out_size) {
    const float* x  = (const float*)d_in[0];   // [256,512,512]
    const float* Wk = (const float*)d_in[1];   // [1024,64,256]
    const float* bk = (const float*)d_in[2];   // [1024,64]
    float* out = (float*)d_out;                // [256, 65536]

    cudaFuncSetAttribute(compression_mma_kernel,
                         cudaFuncAttributeMaxDynamicSharedMemorySize, S_TOTAL);

    compression_mma_kernel<<<1024, NTHREADS, S_TOTAL>>>(x, Wk, bk, out);
}